// round 1
// baseline (speedup 1.0000x reference)
#include <cuda_runtime.h>

#define TOKENS 8192
#define DIN    1024
#define E3     3072
#define HEADS  16
#define DH     64
#define SEQ    2048
#define BATCH  4

// Scratch for the QKV projection result: [8192 tokens][3072]
__device__ float g_qkv[(size_t)TOKENS * E3];

// ---------------------------------------------------------------------------
// Kernel 1: QKV GEMM  out[t][e] = sum_d X[t][d] * W[d][e] + bias[e]
// 128x128 block tile, BK=16, 256 threads, 8x8 microtile (split 4+4 at +64).
// ---------------------------------------------------------------------------
__global__ void __launch_bounds__(256, 2) qkv_gemm_kernel(
    const float* __restrict__ X, const float* __restrict__ W,
    const float* __restrict__ bias) {
  __shared__ float As[16][128];  // transposed: As[k][m]
  __shared__ float Bs[16][128];  // Bs[k][n]

  const int tid = threadIdx.x;
  const int tx = tid & 15;
  const int ty = tid >> 4;
  const int m0 = blockIdx.y * 128;
  const int n0 = blockIdx.x * 128;

  float acc[8][8];
#pragma unroll
  for (int i = 0; i < 8; i++)
#pragma unroll
    for (int j = 0; j < 8; j++) acc[i][j] = 0.f;

  const float* Xb = X + (size_t)m0 * DIN;
  const float* Wb = W + n0;

  for (int k0 = 0; k0 < DIN; k0 += 16) {
#pragma unroll
    for (int it = 0; it < 2; it++) {
      int idx = tid + it * 256;
      int row = idx >> 2;     // 0..127
      int c4  = idx & 3;      // 0..3
      float4 v = *(const float4*)(Xb + (size_t)row * DIN + k0 + c4 * 4);
      As[c4 * 4 + 0][row] = v.x;
      As[c4 * 4 + 1][row] = v.y;
      As[c4 * 4 + 2][row] = v.z;
      As[c4 * 4 + 3][row] = v.w;
    }
#pragma unroll
    for (int it = 0; it < 2; it++) {
      int idx = tid + it * 256;
      int row = idx >> 5;     // 0..15
      int c4  = idx & 31;     // 0..31
      *(float4*)(&Bs[row][c4 * 4]) =
          *(const float4*)(Wb + (size_t)(k0 + row) * E3 + c4 * 4);
    }
    __syncthreads();

#pragma unroll
    for (int k = 0; k < 16; k++) {
      float4 a0 = *(const float4*)&As[k][4 * ty];
      float4 a1 = *(const float4*)&As[k][4 * ty + 64];
      float4 b0 = *(const float4*)&Bs[k][4 * tx];
      float4 b1 = *(const float4*)&Bs[k][4 * tx + 64];
      float av[8] = {a0.x, a0.y, a0.z, a0.w, a1.x, a1.y, a1.z, a1.w};
      float bv[8] = {b0.x, b0.y, b0.z, b0.w, b1.x, b1.y, b1.z, b1.w};
#pragma unroll
      for (int i = 0; i < 8; i++)
#pragma unroll
        for (int j = 0; j < 8; j++) acc[i][j] += av[i] * bv[j];
    }
    __syncthreads();
  }

  // Epilogue: +bias, write to g_qkv
#pragma unroll
  for (int ih = 0; ih < 2; ih++) {
#pragma unroll
    for (int i = 0; i < 4; i++) {
      int row = m0 + ih * 64 + 4 * ty + i;
      float* orow = g_qkv + (size_t)row * E3 + n0;
#pragma unroll
      for (int jh = 0; jh < 2; jh++) {
        int cb = jh * 64 + 4 * tx;
        float4 bb = *(const float4*)(bias + n0 + cb);
        float4 r;
        r.x = acc[ih * 4 + i][jh * 4 + 0] + bb.x;
        r.y = acc[ih * 4 + i][jh * 4 + 1] + bb.y;
        r.z = acc[ih * 4 + i][jh * 4 + 2] + bb.z;
        r.w = acc[ih * 4 + i][jh * 4 + 3] + bb.w;
        *(float4*)(orow + cb) = r;
      }
    }
  }
}

// ---------------------------------------------------------------------------
// Kernel 2: flash attention per (b, h, 64-query block). fp32, online softmax.
// qkv layout per token: [h*192 + {0..63}=Q, {64..127}=K, {128..191}=V]
// smem: QT [64d][68] (d-major), KV (K: d-major [64][68], then V natural
// [64][68]), PT [64c][65] (c-major). All compute-phase reads conflict-free or
// 2-way max.
// ---------------------------------------------------------------------------
#define ATTN_SMEM_FLOATS (2 * 64 * 68 + 64 * 65)
#define ATTN_SMEM_BYTES  (ATTN_SMEM_FLOATS * 4)

__global__ void __launch_bounds__(256, 2) attn_kernel(float* __restrict__ out) {
  extern __shared__ float sm[];
  float* QT = sm;                 // [64][68] indexed [d][r]
  float* KV = sm + 64 * 68;       // K: [d][c]; later V: [c][d], both pad 68
  float* PT = sm + 2 * 64 * 68;   // [c][r], pad 65

  const int tid = threadIdx.x;
  const int tx = tid & 15;
  const int ty = tid >> 4;
  const int bh = blockIdx.y;
  const int b = bh >> 4;
  const int h = bh & 15;
  const float* base = g_qkv + (size_t)b * SEQ * E3 + h * (3 * DH);
  const int q0 = blockIdx.x * 64;

  // Load Q transposed: QT[d][r]
  {
    const float* Qg = base + (size_t)q0 * E3;
#pragma unroll
    for (int it = 0; it < 4; it++) {
      int idx = tid + it * 256;
      int r  = idx & 63;
      int c4 = idx >> 6;   // 0..15
      float4 v = *(const float4*)(Qg + (size_t)r * E3 + c4 * 4);
      QT[(4 * c4 + 0) * 68 + r] = v.x;
      QT[(4 * c4 + 1) * 68 + r] = v.y;
      QT[(4 * c4 + 2) * 68 + r] = v.z;
      QT[(4 * c4 + 3) * 68 + r] = v.w;
    }
  }

  float m_[4], l_[4], o[4][4];
#pragma unroll
  for (int i = 0; i < 4; i++) {
    m_[i] = -1e30f;
    l_[i] = 0.f;
#pragma unroll
    for (int j = 0; j < 4; j++) o[i][j] = 0.f;
  }

  for (int kt = 0; kt < SEQ / 64; kt++) {
    const float* Kg = base + (size_t)(kt * 64) * E3 + DH;
    __syncthreads();  // previous PV done reading KV / PT
    // Load K transposed: KV[d][c]
#pragma unroll
    for (int it = 0; it < 4; it++) {
      int idx = tid + it * 256;
      int r  = idx & 63;
      int c4 = idx >> 6;
      float4 v = *(const float4*)(Kg + (size_t)r * E3 + c4 * 4);
      KV[(4 * c4 + 0) * 68 + r] = v.x;
      KV[(4 * c4 + 1) * 68 + r] = v.y;
      KV[(4 * c4 + 2) * 68 + r] = v.z;
      KV[(4 * c4 + 3) * 68 + r] = v.w;
    }
    __syncthreads();

    // S = Q @ K^T  (outer product over d)
    float s[4][4];
#pragma unroll
    for (int i = 0; i < 4; i++)
#pragma unroll
      for (int j = 0; j < 4; j++) s[i][j] = 0.f;

#pragma unroll 8
    for (int d = 0; d < 64; d++) {
      float4 q = *(const float4*)&QT[d * 68 + 4 * ty];
      float4 k = *(const float4*)&KV[d * 68 + 4 * tx];
      float qv[4] = {q.x, q.y, q.z, q.w};
      float kv[4] = {k.x, k.y, k.z, k.w};
#pragma unroll
      for (int i = 0; i < 4; i++)
#pragma unroll
        for (int j = 0; j < 4; j++) s[i][j] += qv[i] * kv[j];
    }
    __syncthreads();  // all K reads done; KV can be overwritten with V

    // Load V natural: KV[c][d]
    const float* Vg = base + (size_t)(kt * 64) * E3 + 2 * DH;
#pragma unroll
    for (int it = 0; it < 4; it++) {
      int idx = tid + it * 256;
      int r  = idx >> 4;
      int c4 = idx & 15;
      *(float4*)&KV[r * 68 + c4 * 4] =
          *(const float4*)(Vg + (size_t)r * E3 + c4 * 4);
    }

    // Online softmax (rows owned by 16 threads of same ty = one half-warp)
#pragma unroll
    for (int i = 0; i < 4; i++) {
      float mt = -1e30f;
#pragma unroll
      for (int j = 0; j < 4; j++) {
        s[i][j] *= 0.125f;  // 1/sqrt(64)
        mt = fmaxf(mt, s[i][j]);
      }
#pragma unroll
      for (int off = 8; off; off >>= 1)
        mt = fmaxf(mt, __shfl_xor_sync(0xffffffffu, mt, off));
      float mn = fmaxf(m_[i], mt);
      float al = __expf(m_[i] - mn);
      m_[i] = mn;
      float rs = 0.f;
#pragma unroll
      for (int j = 0; j < 4; j++) {
        float p = __expf(s[i][j] - mn);
        s[i][j] = p;
        rs += p;
      }
#pragma unroll
      for (int off = 8; off; off >>= 1)
        rs += __shfl_xor_sync(0xffffffffu, rs, off);
      l_[i] = l_[i] * al + rs;
#pragma unroll
      for (int j = 0; j < 4; j++) o[i][j] *= al;
    }
    // Write P transposed: PT[c][r]
#pragma unroll
    for (int i = 0; i < 4; i++)
#pragma unroll
      for (int j = 0; j < 4; j++)
        PT[(4 * tx + j) * 65 + 4 * ty + i] = s[i][j];
    __syncthreads();  // V + PT visible

    // O += P @ V
#pragma unroll 8
    for (int c = 0; c < 64; c++) {
      float4 v = *(const float4*)&KV[c * 68 + 4 * tx];
      float p0 = PT[c * 65 + 4 * ty + 0];
      float p1 = PT[c * 65 + 4 * ty + 1];
      float p2 = PT[c * 65 + 4 * ty + 2];
      float p3 = PT[c * 65 + 4 * ty + 3];
      o[0][0] += p0 * v.x; o[0][1] += p0 * v.y; o[0][2] += p0 * v.z; o[0][3] += p0 * v.w;
      o[1][0] += p1 * v.x; o[1][1] += p1 * v.y; o[1][2] += p1 * v.z; o[1][3] += p1 * v.w;
      o[2][0] += p2 * v.x; o[2][1] += p2 * v.y; o[2][2] += p2 * v.z; o[2][3] += p2 * v.w;
      o[3][0] += p3 * v.x; o[3][1] += p3 * v.y; o[3][2] += p3 * v.z; o[3][3] += p3 * v.w;
    }
  }

  // Normalize and write out[b][s][h*64 + d]
#pragma unroll
  for (int i = 0; i < 4; i++) {
    float inv = 1.f / l_[i];
    float4 r = make_float4(o[i][0] * inv, o[i][1] * inv,
                           o[i][2] * inv, o[i][3] * inv);
    *(float4*)(out + (size_t)(b * SEQ + q0 + 4 * ty + i) * 1024 + h * 64 +
               4 * tx) = r;
  }
}

// ---------------------------------------------------------------------------
extern "C" void kernel_launch(void* const* d_in, const int* in_sizes, int n_in,
                              void* d_out, int out_size) {
  (void)in_sizes; (void)n_in; (void)out_size;
  const float* x    = (const float*)d_in[0];
  const float* W    = (const float*)d_in[1];
  const float* bias = (const float*)d_in[2];
  float* out = (float*)d_out;

  cudaFuncSetAttribute(attn_kernel, cudaFuncAttributeMaxDynamicSharedMemorySize,
                       ATTN_SMEM_BYTES);

  qkv_gemm_kernel<<<dim3(E3 / 128, TOKENS / 128), 256>>>(x, W, bias);
  attn_kernel<<<dim3(SEQ / 64, BATCH * HEADS), 256, ATTN_SMEM_BYTES>>>(out);
}

// round 8
// speedup vs baseline: 1.2337x; 1.2337x over previous
#include <cuda_runtime.h>

#define TOKENS 8192
#define DIN    1024
#define E3     3072
#define HEADS  16
#define DH     64
#define SEQ    2048
#define BATCH  4

typedef unsigned long long u64;

__device__ float g_qkv[(size_t)TOKENS * E3];

__device__ __forceinline__ u64 pack2(float x, float y) {
  u64 r;
  asm("mov.b64 %0,{%1,%2};" : "=l"(r) : "f"(x), "f"(y));
  return r;
}
__device__ __forceinline__ void unpack2(u64 v, float& x, float& y) {
  asm("mov.b64 {%0,%1},%2;" : "=f"(x), "=f"(y) : "l"(v));
}
__device__ __forceinline__ void ffma2(u64& d, u64 a, u64 b) {
  asm("fma.rn.f32x2 %0,%1,%2,%0;" : "+l"(d) : "l"(a), "l"(b));
}
__device__ __forceinline__ u64 mul2(u64 a, u64 b) {
  u64 r;
  asm("mul.rn.f32x2 %0,%1,%2;" : "=l"(r) : "l"(a), "l"(b));
  return r;
}

// ---------------------------------------------------------------------------
// Kernel 1: QKV GEMM  out[t][e] = sum_d X[t][d] * W[d][e] + bias[e]
// 128x128 tile, BK=16, 256 threads, 8x8 microtile via fma.rn.f32x2.
// ---------------------------------------------------------------------------
__global__ void __launch_bounds__(256, 2) qkv_gemm_kernel(
    const float* __restrict__ X, const float* __restrict__ W,
    const float* __restrict__ bias) {
  __shared__ float As[16][128];  // As[k][m]
  __shared__ float Bs[16][128];  // Bs[k][n]

  const int tid = threadIdx.x;
  const int tx = tid & 15;
  const int ty = tid >> 4;
  const int m0 = blockIdx.y * 128;
  const int n0 = blockIdx.x * 128;

  u64 acc[8][4];
#pragma unroll
  for (int i = 0; i < 8; i++)
#pragma unroll
    for (int j = 0; j < 4; j++) acc[i][j] = 0ull;

  const float* Xb = X + (size_t)m0 * DIN;
  const float* Wb = W + n0;

  for (int k0 = 0; k0 < DIN; k0 += 16) {
#pragma unroll
    for (int it = 0; it < 2; it++) {
      int idx = tid + it * 256;
      int row = idx >> 2;
      int c4 = idx & 3;
      float4 v = *(const float4*)(Xb + (size_t)row * DIN + k0 + c4 * 4);
      As[c4 * 4 + 0][row] = v.x;
      As[c4 * 4 + 1][row] = v.y;
      As[c4 * 4 + 2][row] = v.z;
      As[c4 * 4 + 3][row] = v.w;
    }
#pragma unroll
    for (int it = 0; it < 2; it++) {
      int idx = tid + it * 256;
      int row = idx >> 5;
      int c4 = idx & 31;
      *(float4*)(&Bs[row][c4 * 4]) =
          *(const float4*)(Wb + (size_t)(k0 + row) * E3 + c4 * 4);
    }
    __syncthreads();

#pragma unroll
    for (int k = 0; k < 16; k++) {
      float4 a0 = *(const float4*)&As[k][4 * ty];
      float4 a1 = *(const float4*)&As[k][4 * ty + 64];
      ulonglong2 b0 = *(const ulonglong2*)&Bs[k][4 * tx];
      ulonglong2 b1 = *(const ulonglong2*)&Bs[k][4 * tx + 64];
      u64 bp[4] = {b0.x, b0.y, b1.x, b1.y};
      float av[8] = {a0.x, a0.y, a0.z, a0.w, a1.x, a1.y, a1.z, a1.w};
#pragma unroll
      for (int i = 0; i < 8; i++) {
        u64 ap = pack2(av[i], av[i]);
#pragma unroll
        for (int jp = 0; jp < 4; jp++) ffma2(acc[i][jp], ap, bp[jp]);
      }
    }
    __syncthreads();
  }

#pragma unroll
  for (int ih = 0; ih < 2; ih++) {
#pragma unroll
    for (int i = 0; i < 4; i++) {
      int row = m0 + ih * 64 + 4 * ty + i;
      float* orow = g_qkv + (size_t)row * E3 + n0;
#pragma unroll
      for (int jh = 0; jh < 2; jh++) {
        int cb = jh * 64 + 4 * tx;
        float4 bb = *(const float4*)(bias + n0 + cb);
        float e0, e1, e2, e3;
        unpack2(acc[ih * 4 + i][jh * 2 + 0], e0, e1);
        unpack2(acc[ih * 4 + i][jh * 2 + 1], e2, e3);
        float4 r = make_float4(e0 + bb.x, e1 + bb.y, e2 + bb.z, e3 + bb.w);
        *(float4*)(orow + cb) = r;
      }
    }
  }
}

// ---------------------------------------------------------------------------
// Kernel 2: flash attention, 128-query x 128-key tiles, 8x8 microtile S,
// 8x4 microtile O, fp32x2 packed FMA. One CTA per (b, h, 128-query block).
// smem: QT[64][132] (d-major), KP = K[64][132] (d-major) aliased with
// PT[128][132] (c-major), V[128][68] natural.
// ---------------------------------------------------------------------------
#define QB 128
#define KB 128
#define ATTN_KP_OFF (64 * 132)
#define ATTN_V_OFF  (64 * 132 + 128 * 132)
#define ATTN_SMEM_FLOATS (64 * 132 + 128 * 132 + 128 * 68)
#define ATTN_SMEM_BYTES  (ATTN_SMEM_FLOATS * 4)
// 0.125 (1/sqrt(64)) * log2(e)
#define CSC 0.18033688011112042f

__global__ void __launch_bounds__(256, 1) attn_kernel(float* __restrict__ out) {
  extern __shared__ float sm[];
  float* QT = sm;
  float* KP = sm + ATTN_KP_OFF;
  float* V  = sm + ATTN_V_OFF;

  const int tid = threadIdx.x;
  const int tx = tid & 15;
  const int ty = tid >> 4;
  const int bh = blockIdx.y;
  const int b = bh >> 4;
  const int h = bh & 15;
  const float* base = g_qkv + (size_t)b * SEQ * E3 + h * (3 * DH);
  const int q0 = blockIdx.x * QB;

  // Load Q transposed: QT[d][r], r in [0,128)
  {
    const float* Qg = base + (size_t)q0 * E3;
#pragma unroll
    for (int it = 0; it < 8; it++) {
      int idx = tid + it * 256;
      int r = idx & 127;
      int c4 = idx >> 7;  // 0..15
      float4 v = *(const float4*)(Qg + (size_t)r * E3 + c4 * 4);
      QT[(4 * c4 + 0) * 132 + r] = v.x;
      QT[(4 * c4 + 1) * 132 + r] = v.y;
      QT[(4 * c4 + 2) * 132 + r] = v.z;
      QT[(4 * c4 + 3) * 132 + r] = v.w;
    }
  }

  float m_[8], l_[8];
  u64 o[8][2];
#pragma unroll
  for (int i = 0; i < 8; i++) {
    m_[i] = -1e30f;
    l_[i] = 0.f;
    o[i][0] = 0ull;
    o[i][1] = 0ull;
  }

  for (int kt = 0; kt < SEQ / KB; kt++) {
    const float* Kg = base + (size_t)(kt * KB) * E3 + DH;
    const float* Vg = Kg + DH;
    __syncthreads();  // prior PV done reading KP(=PT) and V
    // K transposed into KP[d][c]
#pragma unroll
    for (int it = 0; it < 8; it++) {
      int idx = tid + it * 256;
      int r = idx & 127;
      int c4 = idx >> 7;
      float4 v = *(const float4*)(Kg + (size_t)r * E3 + c4 * 4);
      KP[(4 * c4 + 0) * 132 + r] = v.x;
      KP[(4 * c4 + 1) * 132 + r] = v.y;
      KP[(4 * c4 + 2) * 132 + r] = v.z;
      KP[(4 * c4 + 3) * 132 + r] = v.w;
    }
    // V natural: V[c][d]
#pragma unroll
    for (int it = 0; it < 8; it++) {
      int idx = tid + it * 256;
      int r = idx >> 4;
      int c4 = idx & 15;
      *(float4*)&V[r * 68 + c4 * 4] =
          *(const float4*)(Vg + (size_t)r * E3 + c4 * 4);
    }
    __syncthreads();

    // S = Q @ K^T : 8x8 per thread (rows 4ty(+64), cols 4tx(+64))
    u64 s[8][4];
#pragma unroll
    for (int i = 0; i < 8; i++)
#pragma unroll
      for (int jp = 0; jp < 4; jp++) s[i][jp] = 0ull;

#pragma unroll 4
    for (int d = 0; d < 64; d++) {
      float4 qA = *(const float4*)&QT[d * 132 + 4 * ty];
      float4 qB = *(const float4*)&QT[d * 132 + 4 * ty + 64];
      ulonglong2 kA = *(const ulonglong2*)&KP[d * 132 + 4 * tx];
      ulonglong2 kB = *(const ulonglong2*)&KP[d * 132 + 4 * tx + 64];
      u64 kp[4] = {kA.x, kA.y, kB.x, kB.y};
      float qv[8] = {qA.x, qA.y, qA.z, qA.w, qB.x, qB.y, qB.z, qB.w};
#pragma unroll
      for (int i = 0; i < 8; i++) {
        u64 ap = pack2(qv[i], qv[i]);
#pragma unroll
        for (int jp = 0; jp < 4; jp++) ffma2(s[i][jp], ap, kp[jp]);
      }
    }

    // Online softmax. Row i owned by 16 tx lanes of a half-warp.
    float p[8][8];
#pragma unroll
    for (int i = 0; i < 8; i++) {
      float f[8];
      unpack2(s[i][0], f[0], f[1]);
      unpack2(s[i][1], f[2], f[3]);
      unpack2(s[i][2], f[4], f[5]);
      unpack2(s[i][3], f[6], f[7]);
      float mt = f[0];
#pragma unroll
      for (int j = 1; j < 8; j++) mt = fmaxf(mt, f[j]);
#pragma unroll
      for (int off = 8; off; off >>= 1)
        mt = fmaxf(mt, __shfl_xor_sync(0xffffffffu, mt, off));
      float mn = fmaxf(m_[i], mt);
      float al = exp2f((m_[i] - mn) * CSC);
      m_[i] = mn;
      float rs = 0.f;
#pragma unroll
      for (int j = 0; j < 8; j++) {
        float pv = exp2f((f[j] - mn) * CSC);
        p[i][j] = pv;
        rs += pv;
      }
#pragma unroll
      for (int off = 8; off; off >>= 1)
        rs += __shfl_xor_sync(0xffffffffu, rs, off);
      l_[i] = l_[i] * al + rs;
      u64 alp = pack2(al, al);
      o[i][0] = mul2(o[i][0], alp);
      o[i][1] = mul2(o[i][1], alp);
    }
    __syncthreads();  // S-loop reads of KP done -> safe to overwrite with PT

    // PT[c][r] writes: 16 x STS.128
#pragma unroll
    for (int jh = 0; jh < 2; jh++)
#pragma unroll
      for (int jj = 0; jj < 4; jj++) {
        int c = 4 * tx + jj + 64 * jh;
        int jc = jh * 4 + jj;
#pragma unroll
        for (int ih = 0; ih < 2; ih++) {
          float4 w = make_float4(p[ih * 4 + 0][jc], p[ih * 4 + 1][jc],
                                 p[ih * 4 + 2][jc], p[ih * 4 + 3][jc]);
          *(float4*)&KP[c * 132 + 4 * ty + 64 * ih] = w;
        }
      }
    __syncthreads();

    // O += P @ V : thread owns rows 4ty(+64), dh cols 4tx (2 pairs)
#pragma unroll 4
    for (int c = 0; c < 128; c++) {
      ulonglong2 vv = *(const ulonglong2*)&V[c * 68 + 4 * tx];
      float4 pA = *(const float4*)&KP[c * 132 + 4 * ty];
      float4 pB = *(const float4*)&KP[c * 132 + 4 * ty + 64];
      float pv[8] = {pA.x, pA.y, pA.z, pA.w, pB.x, pB.y, pB.z, pB.w};
#pragma unroll
      for (int i = 0; i < 8; i++) {
        u64 pp = pack2(pv[i], pv[i]);
        ffma2(o[i][0], pp, vv.x);
        ffma2(o[i][1], pp, vv.y);
      }
    }
  }

  // Normalize and store: out[b][s][h*64 + dh]
#pragma unroll
  for (int i = 0; i < 8; i++) {
    float inv = 1.f / l_[i];
    float e0, e1, e2, e3;
    unpack2(o[i][0], e0, e1);
    unpack2(o[i][1], e2, e3);
    float4 r = make_float4(e0 * inv, e1 * inv, e2 * inv, e3 * inv);
    int row = q0 + 4 * ty + (i >> 2) * 64 + (i & 3);
    *(float4*)(out + (size_t)(b * SEQ + row) * 1024 + h * 64 + 4 * tx) = r;
  }
}

// ---------------------------------------------------------------------------
extern "C" void kernel_launch(void* const* d_in, const int* in_sizes, int n_in,
                              void* d_out, int out_size) {
  (void)in_sizes; (void)n_in; (void)out_size;
  const float* x    = (const float*)d_in[0];
  const float* W    = (const float*)d_in[1];
  const float* bias = (const float*)d_in[2];
  float* out = (float*)d_out;

  cudaFuncSetAttribute(attn_kernel, cudaFuncAttributeMaxDynamicSharedMemorySize,
                       ATTN_SMEM_BYTES);

  qkv_gemm_kernel<<<dim3(E3 / 128, TOKENS / 128), 256>>>(x, W, bias);
  attn_kernel<<<dim3(SEQ / QB, BATCH * HEADS), 256, ATTN_SMEM_BYTES>>>(out);
}

// round 14
// speedup vs baseline: 1.3258x; 1.0747x over previous
#include <cuda_runtime.h>
#include <cuda_bf16.h>

#define TOKENS 8192
#define DIN    1024
#define E3     3072
#define HEADS  16
#define DH     64
#define SEQ    2048
#define BATCH  4

typedef unsigned long long u64;
typedef unsigned int u32;

__device__ float g_qkv[(size_t)TOKENS * E3];
__device__ __nv_bfloat16 g_xhi[(size_t)TOKENS * DIN];
__device__ __nv_bfloat16 g_xlo[(size_t)TOKENS * DIN];
__device__ __nv_bfloat16 g_whi[(size_t)DIN * E3];
__device__ __nv_bfloat16 g_wlo[(size_t)DIN * E3];

__device__ __forceinline__ u64 pack2(float x, float y) {
  u64 r;
  asm("mov.b64 %0,{%1,%2};" : "=l"(r) : "f"(x), "f"(y));
  return r;
}
__device__ __forceinline__ void unpack2(u64 v, float& x, float& y) {
  asm("mov.b64 {%0,%1},%2;" : "=f"(x), "=f"(y) : "l"(v));
}
__device__ __forceinline__ void ffma2(u64& d, u64 a, u64 b) {
  asm("fma.rn.f32x2 %0,%1,%2,%0;" : "+l"(d) : "l"(a), "l"(b));
}
__device__ __forceinline__ u64 mul2(u64 a, u64 b) {
  u64 r;
  asm("mul.rn.f32x2 %0,%1,%2;" : "=l"(r) : "l"(a), "l"(b));
  return r;
}
__device__ __forceinline__ u32 su32(const void* p) {
  u32 a;
  asm("{.reg .u64 t; cvta.to.shared.u64 t,%1; cvt.u32.u64 %0,t;}"
      : "=r"(a) : "l"(p));
  return a;
}
__device__ __forceinline__ void mma_bf16(float* d, const u32* a, const u32* b) {
  asm("mma.sync.aligned.m16n8k16.row.col.f32.bf16.bf16.f32 "
      "{%0,%1,%2,%3},{%4,%5,%6,%7},{%8,%9},{%0,%1,%2,%3};"
      : "+f"(d[0]), "+f"(d[1]), "+f"(d[2]), "+f"(d[3])
      : "r"(a[0]), "r"(a[1]), "r"(a[2]), "r"(a[3]), "r"(b[0]), "r"(b[1]));
}
__device__ __forceinline__ void ldsm_x4(u32* r, u32 addr) {
  asm("ldmatrix.sync.aligned.m8n8.x4.shared.b16 {%0,%1,%2,%3},[%4];"
      : "=r"(r[0]), "=r"(r[1]), "=r"(r[2]), "=r"(r[3]) : "r"(addr));
}
__device__ __forceinline__ void ldsm_x2t(u32* r, u32 addr) {
  asm("ldmatrix.sync.aligned.m8n8.x2.trans.shared.b16 {%0,%1},[%2];"
      : "=r"(r[0]), "=r"(r[1]) : "r"(addr));
}

// ---------------------------------------------------------------------------
// Kernel 0: split fp32 -> (bf16 hi, bf16 lo) planes for X and W.
// ---------------------------------------------------------------------------
__device__ __forceinline__ void split_store(__nv_bfloat16* hi, __nv_bfloat16* lo,
                                            int i, float4 v) {
  float f[4] = {v.x, v.y, v.z, v.w};
  unsigned short h[4], l[4];
#pragma unroll
  for (int k = 0; k < 4; k++) {
    __nv_bfloat16 bh = __float2bfloat16(f[k]);
    h[k] = __bfloat16_as_ushort(bh);
    float r = f[k] - __bfloat162float(bh);
    l[k] = __bfloat16_as_ushort(__float2bfloat16(r));
  }
  ((uint2*)hi)[i] = make_uint2((u32)h[0] | ((u32)h[1] << 16),
                               (u32)h[2] | ((u32)h[3] << 16));
  ((uint2*)lo)[i] = make_uint2((u32)l[0] | ((u32)l[1] << 16),
                               (u32)l[2] | ((u32)l[3] << 16));
}

__global__ void convert_kernel(const float* __restrict__ X,
                               const float* __restrict__ W) {
  const int NX4 = TOKENS * DIN / 4;
  const int NW4 = DIN * E3 / 4;
  int i = blockIdx.x * blockDim.x + threadIdx.x;
  if (i < NX4) {
    split_store(g_xhi, g_xlo, i, ((const float4*)X)[i]);
  } else {
    int j = i - NX4;
    if (j < NW4) split_store(g_whi, g_wlo, j, ((const float4*)W)[j]);
  }
}

// ---------------------------------------------------------------------------
// Kernel 1: QKV GEMM via mma.sync bf16 split-precision (hi*hi+hi*lo+lo*hi).
// Block 128x128, k-tile 32, 8 warps (2m x 4n), warp tile 64x32.
// ---------------------------------------------------------------------------
#define AS 40   // A smem k-stride (bf16)
#define BS 136  // B smem n-stride (bf16)

__global__ void __launch_bounds__(256, 1) qkv_mma_kernel(
    const float* __restrict__ bias) {
  __shared__ __nv_bfloat16 Ah[128 * AS], Al[128 * AS];
  __shared__ __nv_bfloat16 Bh[32 * BS], Bl[32 * BS];

  const int tid = threadIdx.x;
  const int lane = tid & 31;
  const int wid = tid >> 5;
  const int wm = wid & 1;   // 0..1
  const int wn = wid >> 1;  // 0..3
  const int m0 = blockIdx.y * 128;
  const int n0 = blockIdx.x * 128;
  const int g = lane >> 2, t = lane & 3;

  float acc[4][4][4];
#pragma unroll
  for (int i = 0; i < 4; i++)
#pragma unroll
    for (int j = 0; j < 4; j++)
#pragma unroll
      for (int q = 0; q < 4; q++) acc[i][j][q] = 0.f;

  const u32 ah_b = su32(Ah), al_b = su32(Al);
  const u32 bh_b = su32(Bh), bl_b = su32(Bl);

  // ldmatrix lane-address components
  const int li = lane & 7, ls = lane >> 3;
  const int a_r = li + (ls & 1) * 8;   // row within 16
  const int a_c = (ls >> 1) * 8;       // col offset within 16
  const int lb = lane & 15;            // B: row kb+lb

  for (int k0 = 0; k0 < DIN; k0 += 32) {
    __syncthreads();
#pragma unroll
    for (int it = 0; it < 2; it++) {
      int idx = tid + it * 256;      // 0..511
      int row = idx >> 2, kq = idx & 3;
      *(uint4*)(Ah + row * AS + kq * 8) =
          *(const uint4*)(g_xhi + (size_t)(m0 + row) * DIN + k0 + kq * 8);
      *(uint4*)(Al + row * AS + kq * 8) =
          *(const uint4*)(g_xlo + (size_t)(m0 + row) * DIN + k0 + kq * 8);
    }
#pragma unroll
    for (int it = 0; it < 2; it++) {
      int idx = tid + it * 256;      // 0..511
      int kr = idx >> 4, nc = idx & 15;
      *(uint4*)(Bh + kr * BS + nc * 8) =
          *(const uint4*)(g_whi + (size_t)(k0 + kr) * E3 + n0 + nc * 8);
      *(uint4*)(Bl + kr * BS + nc * 8) =
          *(const uint4*)(g_wlo + (size_t)(k0 + kr) * E3 + n0 + nc * 8);
    }
    __syncthreads();

#pragma unroll
    for (int ks = 0; ks < 2; ks++) {
      int kb = ks * 16;
      u32 ah[4][4], al[4][4], bh[4][2], bl[4][2];
#pragma unroll
      for (int i = 0; i < 4; i++) {
        int off = (wm * 64 + i * 16 + a_r) * AS + kb + a_c;  // bf16 idx
        ldsm_x4(ah[i], ah_b + off * 2);
        ldsm_x4(al[i], al_b + off * 2);
      }
#pragma unroll
      for (int j = 0; j < 4; j++) {
        int off = (kb + lb) * BS + wn * 32 + j * 8;
        ldsm_x2t(bh[j], bh_b + off * 2);
        ldsm_x2t(bl[j], bl_b + off * 2);
      }
#pragma unroll
      for (int i = 0; i < 4; i++)
#pragma unroll
        for (int j = 0; j < 4; j++) {
          mma_bf16(acc[i][j], ah[i], bh[j]);
          mma_bf16(acc[i][j], ah[i], bl[j]);
          mma_bf16(acc[i][j], al[i], bh[j]);
        }
    }
  }

  // epilogue: +bias -> g_qkv
#pragma unroll
  for (int i = 0; i < 4; i++) {
    int r = m0 + wm * 64 + i * 16 + g;
#pragma unroll
    for (int j = 0; j < 4; j++) {
      int col = n0 + wn * 32 + j * 8 + 2 * t;
      float2 bb = *(const float2*)(bias + col);
      float2 w0 = make_float2(acc[i][j][0] + bb.x, acc[i][j][1] + bb.y);
      float2 w1 = make_float2(acc[i][j][2] + bb.x, acc[i][j][3] + bb.y);
      *(float2*)(g_qkv + (size_t)r * E3 + col) = w0;
      *(float2*)(g_qkv + (size_t)(r + 8) * E3 + col) = w1;
    }
  }
}

// ---------------------------------------------------------------------------
// Kernel 2: flash attention, 64-query x 128-key tiles, 4x8 microtile S,
// fp32x2 FMA, 2 CTAs/SM (84KB smem). PT stored r-major (conflict-free).
// smem: QT[64d][68], R = KT[64d][132c] aliased with PT[64r][132c], V[128][68].
// ---------------------------------------------------------------------------
#define QB 64
#define KB 128
#define ATTN_R_OFF  (64 * 68)
#define ATTN_V_OFF  (64 * 68 + 64 * 132)
#define ATTN_SMEM_FLOATS (64 * 68 + 64 * 132 + 128 * 68)
#define ATTN_SMEM_BYTES  (ATTN_SMEM_FLOATS * 4)
#define CSC 0.18033688011112042f  // (1/8) * log2(e)

__global__ void __launch_bounds__(256, 2) attn_kernel(float* __restrict__ out) {
  extern __shared__ float sm[];
  float* QT = sm;                // [64][68]  d-major
  float* KT = sm + ATTN_R_OFF;   // [64][132] d-major (K)
  float* PT = sm + ATTN_R_OFF;   // [64][132] r-major (P) -- alias
  float* V  = sm + ATTN_V_OFF;   // [128][68] natural

  const int tid = threadIdx.x;
  const int tx = tid & 15;
  const int ty = tid >> 4;       // rows 4ty..4ty+3 (0..63)
  const int bh = blockIdx.y;
  const int b = bh >> 4;
  const int h = bh & 15;
  const float* base = g_qkv + (size_t)b * SEQ * E3 + h * (3 * DH);
  const int q0 = blockIdx.x * QB;

  // Q transposed: QT[d][r]
  {
    const float* Qg = base + (size_t)q0 * E3;
#pragma unroll
    for (int it = 0; it < 4; it++) {
      int idx = tid + it * 256;   // 0..1023
      int r = idx & 63;
      int c4 = idx >> 6;          // 0..15
      float4 v = *(const float4*)(Qg + (size_t)r * E3 + c4 * 4);
      QT[(4 * c4 + 0) * 68 + r] = v.x;
      QT[(4 * c4 + 1) * 68 + r] = v.y;
      QT[(4 * c4 + 2) * 68 + r] = v.z;
      QT[(4 * c4 + 3) * 68 + r] = v.w;
    }
  }

  float m_[4], l_[4];
  u64 o[4][2];
#pragma unroll
  for (int i = 0; i < 4; i++) {
    m_[i] = -1e30f;
    l_[i] = 0.f;
    o[i][0] = 0ull;
    o[i][1] = 0ull;
  }

  for (int kt = 0; kt < SEQ / KB; kt++) {
    const float* Kg = base + (size_t)(kt * KB) * E3 + DH;
    const float* Vg = Kg + DH;
    __syncthreads();  // prior PV done with PT and V
    // K transposed: KT[d][c]
#pragma unroll
    for (int it = 0; it < 8; it++) {
      int idx = tid + it * 256;   // 0..2047
      int c = idx & 127;
      int c4 = idx >> 7;          // 0..15
      float4 v = *(const float4*)(Kg + (size_t)c * E3 + c4 * 4);
      KT[(4 * c4 + 0) * 132 + c] = v.x;
      KT[(4 * c4 + 1) * 132 + c] = v.y;
      KT[(4 * c4 + 2) * 132 + c] = v.z;
      KT[(4 * c4 + 3) * 132 + c] = v.w;
    }
    // V natural
#pragma unroll
    for (int it = 0; it < 8; it++) {
      int idx = tid + it * 256;
      int r = idx >> 4;           // 0..127
      int c4 = idx & 15;
      *(float4*)&V[r * 68 + c4 * 4] =
          *(const float4*)(Vg + (size_t)r * E3 + c4 * 4);
    }
    __syncthreads();

    // S = Q @ K^T : 4x8 per thread (rows 4ty+i, cols 4tx+j, +64)
    u64 s[4][4];
#pragma unroll
    for (int i = 0; i < 4; i++)
#pragma unroll
      for (int jp = 0; jp < 4; jp++) s[i][jp] = 0ull;

#pragma unroll 4
    for (int d = 0; d < 64; d++) {
      float4 q = *(const float4*)&QT[d * 68 + 4 * ty];
      ulonglong2 kA = *(const ulonglong2*)&KT[d * 132 + 4 * tx];
      ulonglong2 kB = *(const ulonglong2*)&KT[d * 132 + 4 * tx + 64];
      u64 kp[4] = {kA.x, kA.y, kB.x, kB.y};
      float qv[4] = {q.x, q.y, q.z, q.w};
#pragma unroll
      for (int i = 0; i < 4; i++) {
        u64 ap = pack2(qv[i], qv[i]);
#pragma unroll
        for (int jp = 0; jp < 4; jp++) ffma2(s[i][jp], ap, kp[jp]);
      }
    }

    // Online softmax (row owned by 16 tx lanes of a half-warp)
    float p[4][8];
#pragma unroll
    for (int i = 0; i < 4; i++) {
      float f[8];
      unpack2(s[i][0], f[0], f[1]);
      unpack2(s[i][1], f[2], f[3]);
      unpack2(s[i][2], f[4], f[5]);
      unpack2(s[i][3], f[6], f[7]);
      float mt = f[0];
#pragma unroll
      for (int j = 1; j < 8; j++) mt = fmaxf(mt, f[j]);
#pragma unroll
      for (int off = 8; off; off >>= 1)
        mt = fmaxf(mt, __shfl_xor_sync(0xffffffffu, mt, off));
      float mn = fmaxf(m_[i], mt);
      float al = exp2f((m_[i] - mn) * CSC);
      m_[i] = mn;
      float rs = 0.f;
#pragma unroll
      for (int j = 0; j < 8; j++) {
        float pv = exp2f((f[j] - mn) * CSC);
        p[i][j] = pv;
        rs += pv;
      }
#pragma unroll
      for (int off = 8; off; off >>= 1)
        rs += __shfl_xor_sync(0xffffffffu, rs, off);
      l_[i] = l_[i] * al + rs;
      u64 alp = pack2(al, al);
      o[i][0] = mul2(o[i][0], alp);
      o[i][1] = mul2(o[i][1], alp);
    }
    __syncthreads();  // S-loop reads of KT done

    // P stored r-major: PT[r][c] -- conflict-free STS.128
#pragma unroll
    for (int i = 0; i < 4; i++) {
      *(float4*)&PT[(4 * ty + i) * 132 + 4 * tx] =
          make_float4(p[i][0], p[i][1], p[i][2], p[i][3]);
      *(float4*)&PT[(4 * ty + i) * 132 + 4 * tx + 64] =
          make_float4(p[i][4], p[i][5], p[i][6], p[i][7]);
    }
    __syncthreads();

    // O += P @ V : rows 4ty+i, dh cols 4tx..4tx+3 (2 f32 pairs)
#pragma unroll 2
    for (int c = 0; c < 128; c += 2) {
      ulonglong2 v0 = *(const ulonglong2*)&V[c * 68 + 4 * tx];
      ulonglong2 v1 = *(const ulonglong2*)&V[(c + 1) * 68 + 4 * tx];
#pragma unroll
      for (int i = 0; i < 4; i++) {
        float2 pp = *(const float2*)&PT[(4 * ty + i) * 132 + c];
        u64 p0 = pack2(pp.x, pp.x);
        u64 p1 = pack2(pp.y, pp.y);
        ffma2(o[i][0], p0, v0.x);
        ffma2(o[i][1], p0, v0.y);
        ffma2(o[i][0], p1, v1.x);
        ffma2(o[i][1], p1, v1.y);
      }
    }
  }

  // Normalize and store: out[b][s][h*64 + dh]
#pragma unroll
  for (int i = 0; i < 4; i++) {
    float inv = 1.f / l_[i];
    float e0, e1, e2, e3;
    unpack2(o[i][0], e0, e1);
    unpack2(o[i][1], e2, e3);
    float4 r = make_float4(e0 * inv, e1 * inv, e2 * inv, e3 * inv);
    int row = q0 + 4 * ty + i;
    *(float4*)(out + (size_t)(b * SEQ + row) * 1024 + h * 64 + 4 * tx) = r;
  }
}

// ---------------------------------------------------------------------------
extern "C" void kernel_launch(void* const* d_in, const int* in_sizes, int n_in,
                              void* d_out, int out_size) {
  (void)in_sizes; (void)n_in; (void)out_size;
  const float* x    = (const float*)d_in[0];
  const float* W    = (const float*)d_in[1];
  const float* bias = (const float*)d_in[2];
  float* out = (float*)d_out;

  cudaFuncSetAttribute(attn_kernel, cudaFuncAttributeMaxDynamicSharedMemorySize,
                       ATTN_SMEM_BYTES);

  const int NTOT4 = (TOKENS * DIN + DIN * E3) / 4;
  convert_kernel<<<NTOT4 / 256, 256>>>(x, W);
  qkv_mma_kernel<<<dim3(E3 / 128, TOKENS / 128), 256>>>(bias);
  attn_kernel<<<dim3(SEQ / QB, BATCH * HEADS), 256, ATTN_SMEM_BYTES>>>(out);
}